// round 4
// baseline (speedup 1.0000x reference)
#include <cuda_runtime.h>
#include <math_constants.h>

#define NPTS   8192
#define WID    8193
#define NCH    65536          // 8192 rows * 8 chunks, row-major chunk order
#define NT     64             // finish-stage table size
#define NE     50             // positive-threshold histogram edges
#define KCORR  2048
#define MARGIN 1e-4f
#define CAP    (1 << 19)

// ---------------- device scratch (zero-initialized at load; every kernel
// that dirties a cross-call global restores it before exiting) --------------
__device__ float    d_chunkmax[NCH];
__device__ unsigned d_chist[NE];
__device__ unsigned d_tk1, d_tk2;
__device__ float    d_cutL;      // log-domain gate (conservative)
__device__ float    d_cutV;      // linear-domain candidate cut
__device__ unsigned d_coff[NCH];
__device__ unsigned d_btot[64];
__device__ unsigned d_bbase[64];
__device__ unsigned d_ncand;
__device__ unsigned d_ckey[CAP];
__device__ float    d_cv[CAP];

// ==================== K1: single full 268MB pass ====================
// chunk max of L  +  element histogram vs (logt[n]+MARGIN)  +  fused pick.
// grid 1024: bx&7 = column-chunk, bx>>3 = 64-row group; 8 warps x 8 rows.
__global__ void __launch_bounds__(256) k_pass1(const float* __restrict__ ms,
                                               const float* __restrict__ ref,
                                               const float* __restrict__ src) {
    __shared__ float    s_ls[1024];
    __shared__ float    s_edge[NE];
    __shared__ unsigned s_hist[NE];
    __shared__ unsigned s_last;
    const int c = blockIdx.x & 7, rg = blockIdx.x >> 3;
    const int t = threadIdx.x;

    for (int i = t; i < 1024; i += 256) s_ls[i] = logf(src[c * 1024 + i]);
    if (t < NE) {
        float tv = 0.5f;                        // exact fp32 t -= 0.01f chain
        for (int j = 0; j < t; ++j) tv -= 0.01f;
        s_edge[t] = logf(tv) + MARGIN;
        s_hist[t] = 0u;
    }
    __syncthreads();

    const float eLast = s_edge[NE - 1];
    const int lane = t & 31, w = t >> 5;
    for (int rr = 0; rr < 8; ++rr) {
        const int row = rg * 64 + w * 8 + rr;
        const float lr = logf(ref[row]);
        const float* p = ms + (size_t)row * WID + c * 1024 + lane;
        float m = -CUDART_INF_F;
#pragma unroll
        for (int it = 0; it < 32; ++it) {
            const float L = (p[it * 32] + s_ls[it * 32 + lane]) + lr;
            m = fmaxf(m, L);
            if (L > eLast) {                    // ~8% of elements
                int lo = 0, hi = NE - 1;        // first n with edge[n] < L
                while (lo < hi) { int mid = (lo + hi) >> 1; if (s_edge[mid] < L) hi = mid; else lo = mid + 1; }
                atomicAdd(&s_hist[lo], 1u);
            }
        }
#pragma unroll
        for (int o = 16; o; o >>= 1) m = fmaxf(m, __shfl_xor_sync(0xffffffffu, m, o));
        if (lane == 0) d_chunkmax[row * 8 + c] = m;
    }
    __syncthreads();
    if (t < NE && s_hist[t]) atomicAdd(&d_chist[t], s_hist[t]);
    __threadfence();
    __syncthreads();
    if (t == 0) s_last = (atomicAdd(&d_tk1, 1u) == gridDim.x - 1) ? 1u : 0u;
    __syncthreads();
    if (s_last) {
        if (t < NE) s_hist[t] = atomicAdd(&d_chist[t], 0u);   // strong read
        __syncthreads();
        if (t == 0) {
            unsigned cum = 0; int nup = NE - 1;
            for (int n = 0; n < NE; ++n) { cum += s_hist[n]; if (cum >= KCORR) { nup = n; break; } }
            float tv = 0.5f;
            for (int j = 0; j < nup; ++j) tv -= 0.01f;
            d_cutL = logf(tv) - MARGIN;          // gate: any candidate has L > cutL
            d_cutV = tv * (1.0f - 5e-5f);        // linear cut, certainly < t_nup
            d_tk1  = 0u;                         // restore for next call
        }
        if (t < NE) d_chist[t] = 0u;             // restore for next call
    }
}

// ==================== K2: gated count + block scan + fused base scan =========
// 64 blocks x 1024 threads; warp gates 32 chunks via one coalesced load+ballot.
__global__ void __launch_bounds__(1024) k_countscan(const float* __restrict__ ms,
                                                    const float* __restrict__ ref,
                                                    const float* __restrict__ src) {
    __shared__ unsigned s_cnt[1024];
    __shared__ unsigned s_wsum[32];
    __shared__ unsigned s_tot;
    __shared__ unsigned s_last;
    const int t = threadIdx.x, lane = t & 31, w = t >> 5;
    const int chunk0 = blockIdx.x * 1024 + w * 32;
    const float cutL = d_cutL, cutV = d_cutV;

    s_cnt[t] = 0u;
    const float mymax = d_chunkmax[chunk0 + lane];
    unsigned act = __ballot_sync(0xffffffffu, mymax > cutL);
    while (act) {
        const int i = __ffs(act) - 1; act &= act - 1;
        const int chunk = chunk0 + i;
        const int row = chunk >> 3, ch = chunk & 7;
        const float rr = ref[row];
        const float* p  = ms  + (size_t)row * WID + ch * 1024 + lane;
        const float* ps = src + ch * 1024 + lane;
        unsigned cnt = 0;
#pragma unroll
        for (int it = 0; it < 32; ++it) {
            const float v = expf(p[it * 32]) * (rr * ps[it * 32]);  // exact ref expr
            cnt += (v > cutV) ? 1u : 0u;
        }
#pragma unroll
        for (int o = 16; o; o >>= 1) cnt += __shfl_xor_sync(0xffffffffu, cnt, o);
        if (lane == 0) s_cnt[w * 32 + i] = cnt;
    }
    __syncthreads();

    unsigned v = s_cnt[t], x = v;
#pragma unroll
    for (int o = 1; o < 32; o <<= 1) { unsigned y = __shfl_up_sync(0xffffffffu, x, o); if (lane >= o) x += y; }
    if (lane == 31) s_wsum[w] = x;
    __syncthreads();
    if (w == 0) {
        unsigned a = s_wsum[lane], y = a;
#pragma unroll
        for (int o = 1; o < 32; o <<= 1) { unsigned z = __shfl_up_sync(0xffffffffu, y, o); if (lane >= o) y += z; }
        s_wsum[lane] = y - a;
        if (lane == 31) s_tot = y;
    }
    __syncthreads();
    d_coff[blockIdx.x * 1024 + t] = x - v + s_wsum[w];
    if (t == 0) {
        d_btot[blockIdx.x] = s_tot;
        __threadfence();
        s_last = (atomicAdd(&d_tk2, 1u) == gridDim.x - 1) ? 1u : 0u;
    }
    __syncthreads();
    if (s_last) {
        if (t < 64) s_cnt[t] = atomicAdd(&d_btot[t], 0u);     // strong read
        __syncthreads();
        if (t == 0) {
            unsigned run = 0;
            for (int j = 0; j < 64; ++j) { unsigned cc = s_cnt[j]; d_bbase[j] = run; run += cc; }
            d_ncand = run;
            d_tk2   = 0u;
        }
    }
}

// ==================== K3: gated ordered extraction ====================
// 256 blocks x 256 threads; warp gates 32 chunks; offsets = bbase + coff.
__global__ void __launch_bounds__(256) k_extract(const float* __restrict__ ms,
                                                 const float* __restrict__ ref,
                                                 const float* __restrict__ src) {
    const int t = threadIdx.x, lane = t & 31, w = t >> 5;
    const int chunk0 = (blockIdx.x * 8 + w) * 32;
    const float cutL = d_cutL, cutV = d_cutV;

    const float mymax = d_chunkmax[chunk0 + lane];
    unsigned act = __ballot_sync(0xffffffffu, mymax > cutL);
    while (act) {
        const int i = __ffs(act) - 1; act &= act - 1;
        const int chunk = chunk0 + i;
        const int row = chunk >> 3, ch = chunk & 7;
        const float rr = ref[row];
        const float* p  = ms  + (size_t)row * WID + ch * 1024 + lane;
        const float* ps = src + ch * 1024 + lane;
        float vv[32];
        unsigned pb = 0;
#pragma unroll
        for (int it = 0; it < 32; ++it) {          // batched: full MLP
            vv[it] = expf(p[it * 32]) * (rr * ps[it * 32]);
            pb |= (vv[it] > cutV) ? (1u << it) : 0u;
        }
        unsigned base = d_bbase[chunk >> 10] + d_coff[chunk];
        unsigned cnt = 0;
#pragma unroll
        for (int it = 0; it < 32; ++it) {
            const bool pred = (pb >> it) & 1u;
            const unsigned mk = __ballot_sync(0xffffffffu, pred);
            if (pred) {
                const unsigned pos = base + cnt + __popc(mk & ((1u << lane) - 1u));
                if (pos < CAP) {
                    d_ckey[pos] = ((unsigned)row << 13) | (unsigned)(ch * 1024 + it * 32 + lane);
                    d_cv[pos]   = vv[it];
                }
            }
            cnt += (unsigned)__popc(mk);
        }
    }
}

// ==================== K4: exact pick + ordered output + padding ==============
__global__ void __launch_bounds__(1024) k_finish(float* __restrict__ out, int seg) {
    __shared__ unsigned h[NT];
    __shared__ float    tt[NT];
    __shared__ unsigned ws[32];
    __shared__ float    s_thres;
    __shared__ unsigned s_tot;
    const int t = threadIdx.x, lane = t & 31, wid = t >> 5;
    if (t < NT) {
        float tv = 0.5f;
        for (int j = 0; j < t; ++j) tv -= 0.01f;
        tt[t] = tv;
        h[t] = 0u;
    }
    __syncthreads();
    const unsigned n = min(d_ncand, (unsigned)CAP);

    // exact element histogram over candidates (linear domain)
    for (unsigned i = t; i < n; i += 1024) {
        const float v = d_cv[i];
        int lo = 0, hi = NT - 1;                 // first n with table[n] < v
        while (lo < hi) { int mid = (lo + hi) >> 1; if (tt[mid] < v) hi = mid; else lo = mid + 1; }
        atomicAdd(&h[lo], 1u);
    }
    __syncthreads();
    if (t == 0) {
        unsigned cum = 0; int pick = NT - 1;
        for (int i = 0; i < NT; ++i) { cum += h[i]; if (cum >= KCORR) { pick = i; break; } }
        s_thres = tt[pick];
    }
    __syncthreads();
    const float thres = s_thres;
    const unsigned lim = (unsigned)min(seg, 8192);

    // ordered compaction, 4 elements per thread per tile
    unsigned base = 0;
    for (unsigned start = 0; start < n; start += 4096) {
        float v4[4]; unsigned k4[4]; bool pr[4];
        const unsigned i0 = start + (unsigned)t * 4u;
        unsigned pc = 0;
#pragma unroll
        for (int j = 0; j < 4; ++j) {
            const unsigned i = i0 + j;
            pr[j] = false;
            if (i < n) { v4[j] = d_cv[i]; k4[j] = d_ckey[i]; pr[j] = (v4[j] > thres); pc += pr[j] ? 1u : 0u; }
        }
        unsigned x = pc;
#pragma unroll
        for (int o = 1; o < 32; o <<= 1) { unsigned y = __shfl_up_sync(0xffffffffu, x, o); if (lane >= o) x += y; }
        if (lane == 31) ws[wid] = x;
        __syncthreads();
        if (wid == 0) {
            unsigned v = ws[lane], y = v;
#pragma unroll
            for (int o = 1; o < 32; o <<= 1) { unsigned z = __shfl_up_sync(0xffffffffu, y, o); if (lane >= o) y += z; }
            ws[lane] = y - v;
            if (lane == 31) s_tot = y;
        }
        __syncthreads();
        unsigned slot = base + (x - pc) + ws[wid];
#pragma unroll
        for (int j = 0; j < 4; ++j) {
            if (pr[j]) {
                if (slot < lim) {
                    out[slot]           = (float)(k4[j] >> 13);
                    out[seg + slot]     = (float)(k4[j] & 8191u);
                    out[2 * seg + slot] = v4[j];
                }
                ++slot;
            }
        }
        base += s_tot;
        __syncthreads();
    }
    // padding: valid = idx < count
    for (unsigned i = min(base, lim) + (unsigned)t; i < (unsigned)seg; i += 1024) {
        out[i] = -1.0f; out[seg + i] = -1.0f; out[2 * seg + i] = 0.0f;
    }
}

// ---------------- launch ----------------
extern "C" void kernel_launch(void* const* d_in, const int* in_sizes, int n_in,
                              void* d_out, int out_size) {
    const float* ms  = (const float*)d_in[0];
    const float* ref = (const float*)d_in[1];
    const float* src = (const float*)d_in[2];
    float* out = (float*)d_out;
    const int seg = out_size / 3;

    k_pass1    <<<1024, 256>>>(ms, ref, src);
    k_countscan<<<64, 1024>>>(ms, ref, src);
    k_extract  <<<256, 256>>>(ms, ref, src);
    k_finish   <<<1, 1024>>>(out, seg);
}

// round 5
// speedup vs baseline: 1.8511x; 1.8511x over previous
#include <cuda_runtime.h>
#include <math_constants.h>

#define NPTS   8192
#define WID    8193
#define NCH    65536          // 8192 rows * 8 chunks, row-major chunk order
#define NT     64             // threshold table size (covers t <= 0 fallback)
#define KCORR  2048
#define MARGIN 1e-4f
#define LOGNEG (-1e30f)

// ---------------- device scratch (zero-init at load; each kernel restores
// any cross-call global it dirties) ----------------
__device__ float    d_chunkmax[NCH];
__device__ unsigned d_chist[NT];     // chunk-level hist
__device__ unsigned d_ehist[NT];     // element-level hist (sparse exact)
__device__ unsigned d_tk1, d_tk2, d_tk3;
__device__ float    d_cutL;          // log-domain chunk gate
__device__ float    d_vlow;          // linear floor for hist binning
__device__ float    d_thres;         // exact final threshold
__device__ unsigned d_coff[NCH];     // per-chunk exclusive offset (within block)
__device__ unsigned d_btot[64];
__device__ unsigned d_bbase[64];
__device__ unsigned d_ncand;         // total selected

__device__ __forceinline__ float table_at(int n) {
    float tv = 0.5f;                 // exact fp32 replication of t -= 0.01f
    for (int j = 0; j < n; ++j) tv -= 0.01f;
    return tv;
}

// ==================== K1: single full 268MB pass (PURE inner loop) ==========
// grid 1024: bx&7 = column-chunk, bx>>3 = 64-row group; 8 warps x 8 rows.
__global__ void __launch_bounds__(256) k_pass1(const float* __restrict__ ms,
                                               const float* __restrict__ ref,
                                               const float* __restrict__ src) {
    __shared__ float    s_ls[1024];
    __shared__ float    s_logt[NT];
    __shared__ unsigned s_h[NT];
    __shared__ unsigned s_last;
    const int c = blockIdx.x & 7, rg = blockIdx.x >> 3;
    const int t = threadIdx.x;

    for (int i = t; i < 1024; i += 256) s_ls[i] = logf(src[c * 1024 + i]);
    if (t < NT) {
        const float tv = table_at(t);
        s_logt[t] = (tv > 0.0f) ? logf(tv) : LOGNEG;
        s_h[t] = 0u;
    }
    __syncthreads();

    const int lane = t & 31, w = t >> 5;
    for (int rr = 0; rr < 8; ++rr) {
        const int row = rg * 64 + w * 8 + rr;
        const float lr = logf(ref[row]);
        const float* p = ms + (size_t)row * WID + c * 1024 + lane;
        float m = -CUDART_INF_F;
#pragma unroll
        for (int it = 0; it < 32; ++it)
            m = fmaxf(m, (p[it * 32] + s_ls[it * 32 + lane]) + lr);   // pure: no branches
#pragma unroll
        for (int o = 16; o; o >>= 1) m = fmaxf(m, __shfl_xor_sync(0xffffffffu, m, o));
        if (lane == 0) {
            d_chunkmax[row * 8 + c] = m;
            int lo = 0, hi = NT;      // first n with logt[n]+MARGIN < m
            while (lo < hi) { int mid = (lo + hi) >> 1; if (s_logt[mid] + MARGIN < m) hi = mid; else lo = mid + 1; }
            if (lo < NT) atomicAdd(&s_h[lo], 1u);
        }
    }
    __syncthreads();
    if (t < NT && s_h[t]) atomicAdd(&d_chist[t], s_h[t]);
    __threadfence();
    __syncthreads();
    if (t == 0) s_last = (atomicAdd(&d_tk1, 1u) == gridDim.x - 1) ? 1u : 0u;
    __syncthreads();
    if (s_last) {
        if (t < NT) s_h[t] = atomicAdd(&d_chist[t], 0u);
        __syncthreads();
        if (t == 0) {
            unsigned cum = 0; int nl = NT - 1;
            for (int n = 0; n < NT; ++n) { cum += s_h[n]; if (cum >= KCORR) { nl = n; break; } }
            d_cutL = s_logt[nl] - MARGIN;   // any element that can matter is in a gated chunk
            d_vlow = table_at(nl);          // hist floor
            d_tk1  = 0u;
        }
        if (t < NT) d_chist[t] = 0u;
    }
}

// ==================== K2: sparse exact element histogram + pick ==============
// 64 blocks x 1024 threads; warp gates 32 chunks via one coalesced load+ballot.
__global__ void __launch_bounds__(1024) k_hist(const float* __restrict__ ms,
                                               const float* __restrict__ ref,
                                               const float* __restrict__ src) {
    __shared__ float    tt[NT];
    __shared__ unsigned h[NT];
    __shared__ unsigned s_last;
    const int t = threadIdx.x, lane = t & 31, w = t >> 5;
    if (t < NT) { tt[t] = table_at(t); h[t] = 0u; }
    __syncthreads();
    const int chunk0 = blockIdx.x * 1024 + w * 32;
    const float cutL = d_cutL, vlow = d_vlow;

    unsigned act = __ballot_sync(0xffffffffu, d_chunkmax[chunk0 + lane] > cutL);
    while (act) {
        const int i = __ffs(act) - 1; act &= act - 1;
        const int chunk = chunk0 + i;
        const int row = chunk >> 3, ch = chunk & 7;
        const float rr = ref[row];
        const float* p  = ms  + (size_t)row * WID + ch * 1024 + lane;
        const float* ps = src + ch * 1024 + lane;
#pragma unroll
        for (int it = 0; it < 32; ++it) {
            const float v = expf(p[it * 32]) * (rr * ps[it * 32]);   // exact ref expr
            if (v > vlow) {                 // only bins <= nlow can matter
                int lo = 0, hi = NT - 1;    // first n with table[n] < v
                while (lo < hi) { int mid = (lo + hi) >> 1; if (tt[mid] < v) hi = mid; else lo = mid + 1; }
                atomicAdd(&h[lo], 1u);
            }
        }
    }
    __syncthreads();
    if (t < NT && h[t]) atomicAdd(&d_ehist[t], h[t]);
    __threadfence();
    __syncthreads();
    if (t == 0) s_last = (atomicAdd(&d_tk2, 1u) == gridDim.x - 1) ? 1u : 0u;
    __syncthreads();
    if (s_last) {
        if (t < NT) h[t] = atomicAdd(&d_ehist[t], 0u);
        __syncthreads();
        if (t == 0) {
            unsigned cum = 0; int pick = NT - 1;
            for (int n = 0; n < NT; ++n) { cum += h[n]; if (cum >= KCORR) { pick = n; break; } }
            d_thres = tt[pick];
            d_tk2   = 0u;
        }
        if (t < NT) d_ehist[t] = 0u;
    }
}

// ==================== K3: count at exact thres + scan + base scan ============
__global__ void __launch_bounds__(1024) k_countscan(const float* __restrict__ ms,
                                                    const float* __restrict__ ref,
                                                    const float* __restrict__ src) {
    __shared__ unsigned s_cnt[1024];
    __shared__ unsigned s_wsum[32];
    __shared__ unsigned s_tot;
    __shared__ unsigned s_last;
    const int t = threadIdx.x, lane = t & 31, w = t >> 5;
    const int chunk0 = blockIdx.x * 1024 + w * 32;
    const float cutL = d_cutL, thres = d_thres;

    s_cnt[t] = 0u;
    unsigned act = __ballot_sync(0xffffffffu, d_chunkmax[chunk0 + lane] > cutL);
    while (act) {
        const int i = __ffs(act) - 1; act &= act - 1;
        const int chunk = chunk0 + i;
        const int row = chunk >> 3, ch = chunk & 7;
        const float rr = ref[row];
        const float* p  = ms  + (size_t)row * WID + ch * 1024 + lane;
        const float* ps = src + ch * 1024 + lane;
        unsigned cnt = 0;
#pragma unroll
        for (int it = 0; it < 32; ++it) {
            const float v = expf(p[it * 32]) * (rr * ps[it * 32]);
            cnt += (v > thres) ? 1u : 0u;
        }
#pragma unroll
        for (int o = 16; o; o >>= 1) cnt += __shfl_xor_sync(0xffffffffu, cnt, o);
        if (lane == 0) s_cnt[w * 32 + i] = cnt;
    }
    __syncthreads();

    unsigned v = s_cnt[t], x = v;
#pragma unroll
    for (int o = 1; o < 32; o <<= 1) { unsigned y = __shfl_up_sync(0xffffffffu, x, o); if (lane >= o) x += y; }
    if (lane == 31) s_wsum[w] = x;
    __syncthreads();
    if (w == 0) {
        unsigned a = s_wsum[lane], y = a;
#pragma unroll
        for (int o = 1; o < 32; o <<= 1) { unsigned z = __shfl_up_sync(0xffffffffu, y, o); if (lane >= o) y += z; }
        s_wsum[lane] = y - a;
        if (lane == 31) s_tot = y;
    }
    __syncthreads();
    d_coff[blockIdx.x * 1024 + t] = x - v + s_wsum[w];
    if (t == 0) {
        d_btot[blockIdx.x] = s_tot;
        __threadfence();
        s_last = (atomicAdd(&d_tk3, 1u) == gridDim.x - 1) ? 1u : 0u;
    }
    __syncthreads();
    if (s_last) {
        if (t < 64) s_cnt[t] = atomicAdd(&d_btot[t], 0u);
        __syncthreads();
        if (t == 0) {
            unsigned run = 0;
            for (int j = 0; j < 64; ++j) { unsigned cc = s_cnt[j]; d_bbase[j] = run; run += cc; }
            d_ncand = run;
            d_tk3   = 0u;
        }
    }
}

// ==================== K4: ordered extraction direct to out + padding =========
// 256 blocks x 256 threads; warp gates 32 chunks.
__global__ void __launch_bounds__(256) k_output(const float* __restrict__ ms,
                                                const float* __restrict__ ref,
                                                const float* __restrict__ src,
                                                float* __restrict__ out, int seg) {
    const int t = threadIdx.x, lane = t & 31, w = t >> 5;
    const int chunk0 = (blockIdx.x * 8 + w) * 32;
    const float cutL = d_cutL, thres = d_thres;
    const unsigned lim = (unsigned)min(seg, 8192);

    unsigned act = __ballot_sync(0xffffffffu, d_chunkmax[chunk0 + lane] > cutL);
    while (act) {
        const int i = __ffs(act) - 1; act &= act - 1;
        const int chunk = chunk0 + i;
        const int row = chunk >> 3, ch = chunk & 7;
        const float rr = ref[row];
        const float* p  = ms  + (size_t)row * WID + ch * 1024 + lane;
        const float* ps = src + ch * 1024 + lane;
        float vv[32];
        unsigned pb = 0;
#pragma unroll
        for (int it = 0; it < 32; ++it) {          // batched loads: full MLP
            vv[it] = expf(p[it * 32]) * (rr * ps[it * 32]);
            pb |= (vv[it] > thres) ? (1u << it) : 0u;
        }
        unsigned pos = d_bbase[chunk >> 10] + d_coff[chunk];
#pragma unroll
        for (int it = 0; it < 32; ++it) {
            const bool pred = (pb >> it) & 1u;
            const unsigned mk = __ballot_sync(0xffffffffu, pred);
            if (pred) {
                const unsigned slot = pos + __popc(mk & ((1u << lane) - 1u));
                if (slot < lim) {
                    out[slot]           = (float)row;
                    out[seg + slot]     = (float)(ch * 1024 + it * 32 + lane);
                    out[2 * seg + slot] = vv[it];
                }
            }
            pos += (unsigned)__popc(mk);
        }
    }
    // padding: valid = idx < count  ->  slots >= min(count, lim) get (-1,-1,0)
    const unsigned start = min(d_ncand, lim);
    const unsigned gtid = blockIdx.x * 256 + t, gsz = gridDim.x * 256;
    for (unsigned i = start + gtid; i < (unsigned)seg; i += gsz) {
        out[i] = -1.0f; out[seg + i] = -1.0f; out[2 * seg + i] = 0.0f;
    }
}

// ---------------- launch ----------------
extern "C" void kernel_launch(void* const* d_in, const int* in_sizes, int n_in,
                              void* d_out, int out_size) {
    const float* ms  = (const float*)d_in[0];
    const float* ref = (const float*)d_in[1];
    const float* src = (const float*)d_in[2];
    float* out = (float*)d_out;
    const int seg = out_size / 3;

    k_pass1    <<<1024, 256>>>(ms, ref, src);
    k_hist     <<<64, 1024>>>(ms, ref, src);
    k_countscan<<<64, 1024>>>(ms, ref, src);
    k_output   <<<256, 256>>>(ms, ref, src, out, seg);
}

// round 7
// speedup vs baseline: 1.9699x; 1.0642x over previous
#include <cuda_runtime.h>
#include <math_constants.h>

#define NPTS   8192
#define WID    8193
#define NCH    65536          // 8192 rows * 8 chunks (shifted windows)
#define NT     64
#define KCORR  2048
#define MARGIN 1e-4f
#define LOGNEG (-1e30f)

// ------------- device scratch (zero-init at load; kernels restore what they dirty)
__device__ float    d_logs4[4][NPTS];   // copy s: logf(src[j+s]) or -1e30 pad
__device__ float    d_logr[NPTS];
__device__ float    d_chunkmax[NCH];
__device__ unsigned d_chist[NT];
__device__ unsigned d_ehist[NT];
__device__ unsigned d_tkA, d_tkB, d_tkC, d_tkD;
__device__ unsigned d_flagA, d_flagB;
__device__ float    d_cutL, d_vlow, d_thres;
__device__ unsigned d_coff[NCH];
__device__ unsigned d_btot[64];
__device__ unsigned d_bbase[64];
__device__ unsigned d_ncand;

__device__ __forceinline__ float table_at(int n) {
    float tv = 0.5f;                    // exact fp32 replication of t -= 0.01f
    for (int j = 0; j < n; ++j) tv -= 0.01f;
    return tv;
}

// ==================== K0: log tables (4 shifted copies, padded) ==============
__global__ void k_init(const float* __restrict__ ref, const float* __restrict__ src) {
    const int i = blockIdx.x * 256 + threadIdx.x;   // 0..8191
    if (i < NPTS) {
        d_logr[i] = logf(ref[i]);
#pragma unroll
        for (int s = 0; s < 4; ++s)
            d_logs4[s][i] = (i + s < NPTS) ? logf(src[i + s]) : LOGNEG;
    }
}

// ==================== K1: single full 268MB pass, float4 ====================
// grid 1024: bx&7 = column-chunk, bx>>3 = 64-row group; 8 warps x 8 rows.
// Row r uses shifted window start s=(4-r&3)&3 so loads are 16B-aligned.
__global__ void __launch_bounds__(256) k_pass1(const float* __restrict__ ms) {
    __shared__ float    s_logt[NT];
    __shared__ unsigned s_h[NT];
    __shared__ unsigned s_last;
    const int c = blockIdx.x & 7, rg = blockIdx.x >> 3, t = threadIdx.x;
    if (t < NT) {
        const float tv = table_at(t);
        s_logt[t] = (tv > 0.0f) ? logf(tv) : LOGNEG;
        s_h[t] = 0u;
    }
    __syncthreads();

    const int lane = t & 31, w = t >> 5;
    for (int rr = 0; rr < 8; ++rr) {
        const int row = rg * 64 + w * 8 + rr;
        const int s = (4 - (row & 3)) & 3;
        const float4* __restrict__ p4 =
            (const float4*)(ms + (size_t)row * WID + c * 1024 + s);
        const float4* __restrict__ q4 = (const float4*)(&d_logs4[s][c * 1024]);
        float m = -CUDART_INF_F;
#pragma unroll
        for (int k = 0; k < 8; ++k) {
            const float4 a = p4[k * 32 + lane];
            const float4 b = q4[k * 32 + lane];
            m = fmaxf(m, fmaxf(fmaxf(a.x + b.x, a.y + b.y),
                               fmaxf(a.z + b.z, a.w + b.w)));
        }
        if (c == 0 && lane < s)         // head cols [0,s) fold into chunk 0
            m = fmaxf(m, ms[(size_t)row * WID + lane] + d_logs4[0][lane]);
        m += d_logr[row];               // monotone: still >= every element's L
#pragma unroll
        for (int o = 16; o; o >>= 1) m = fmaxf(m, __shfl_xor_sync(0xffffffffu, m, o));
        if (lane == 0) {
            d_chunkmax[row * 8 + c] = m;
            int lo = 0, hi = NT;        // first n with logt[n]+MARGIN < m
            while (lo < hi) { int mid = (lo + hi) >> 1; if (s_logt[mid] + MARGIN < m) hi = mid; else lo = mid + 1; }
            if (lo < NT) atomicAdd(&s_h[lo], 1u);
        }
    }
    __syncthreads();
    if (t < NT && s_h[t]) atomicAdd(&d_chist[t], s_h[t]);
    __threadfence();
    __syncthreads();
    if (t == 0) s_last = (atomicAdd(&d_tkA, 1u) == gridDim.x - 1) ? 1u : 0u;
    __syncthreads();
    if (s_last) {
        if (t < NT) s_h[t] = atomicAdd(&d_chist[t], 0u);
        __syncthreads();
        if (t == 0) {
            unsigned cum = 0; int nl = NT - 1;
            for (int n = 0; n < NT; ++n) { cum += s_h[n]; if (cum >= KCORR) { nl = n; break; } }
            d_cutL = s_logt[nl] - MARGIN;
            d_vlow = table_at(nl);
            d_tkA  = 0u;
        }
        if (t < NT) d_chist[t] = 0u;
    }
}

// ==================== K2: fused sparse pipeline (hist -> count/scan -> out) ==
// 64 blocks x 1024 threads: all co-resident => internal spin syncs are safe.
__global__ void __launch_bounds__(1024) k_sparse(const float* __restrict__ ms,
                                                 const float* __restrict__ ref,
                                                 const float* __restrict__ src,
                                                 float* __restrict__ out, int seg) {
    __shared__ float    tt[NT];
    __shared__ unsigned h[NT];
    __shared__ unsigned s_cnt[1024];
    __shared__ unsigned s_wsum[32];
    __shared__ unsigned s_tot;
    __shared__ unsigned s_last;
    const int t = threadIdx.x, lane = t & 31, w = t >> 5;
    const int chunk0 = blockIdx.x * 1024 + w * 32;
    if (t < NT) { tt[t] = table_at(t); h[t] = 0u; }
    __syncthreads();

    const float cutL = d_cutL, vlow = d_vlow;
    const unsigned act0 = __ballot_sync(0xffffffffu, d_chunkmax[chunk0 + lane] > cutL);

    // ---------------- phase A: exact element histogram ----------------
    unsigned act = act0;
    while (act) {
        const int i = __ffs(act) - 1; act &= act - 1;
        const int chunk = chunk0 + i;
        const int row = chunk >> 3, c = chunk & 7, s = (4 - (row & 3)) & 3;
        const float rr = ref[row];
        const float* __restrict__ p = ms + (size_t)row * WID;
        if (c == 0 && lane < s) {
            const float v = expf(p[lane]) * (rr * src[lane]);
            if (v > vlow) {
                int lo = 0, hi = NT - 1;
                while (lo < hi) { int mid = (lo + hi) >> 1; if (tt[mid] < v) hi = mid; else lo = mid + 1; }
                atomicAdd(&h[lo], 1u);
            }
        }
        const int col0 = c * 1024 + s + lane;
#pragma unroll
        for (int it = 0; it < 32; ++it) {
            const int col = col0 + it * 32;
            if (col < NPTS) {
                const float v = expf(p[col]) * (rr * src[col]);  // exact ref expr
                if (v > vlow) {
                    int lo = 0, hi = NT - 1;
                    while (lo < hi) { int mid = (lo + hi) >> 1; if (tt[mid] < v) hi = mid; else lo = mid + 1; }
                    atomicAdd(&h[lo], 1u);
                }
            }
        }
    }
    __syncthreads();
    if (t < NT && h[t]) atomicAdd(&d_ehist[t], h[t]);
    __threadfence();
    __syncthreads();
    if (t == 0) s_last = (atomicAdd(&d_tkB, 1u) == gridDim.x - 1) ? 1u : 0u;
    __syncthreads();
    if (s_last) {
        if (t < NT) h[t] = atomicAdd(&d_ehist[t], 0u);
        __syncthreads();
        if (t == 0) {
            unsigned cum = 0; int pick = NT - 1;
            for (int n = 0; n < NT; ++n) { cum += h[n]; if (cum >= KCORR) { pick = n; break; } }
            d_thres = tt[pick];
            d_tkB   = 0u;
        }
        if (t < NT) d_ehist[t] = 0u;
        __threadfence();
        __syncthreads();
        if (t == 0) atomicExch(&d_flagA, 1u);
    }
    if (t == 0) { while (atomicAdd(&d_flagA, 0u) == 0u) __nanosleep(100); }
    __syncthreads();
    __threadfence();
    const float thres = d_thres;

    // ---------------- phase B: count at thres + scan + base scan ----------------
    s_cnt[t] = 0u;
    act = act0;
    while (act) {
        const int i = __ffs(act) - 1; act &= act - 1;
        const int chunk = chunk0 + i;
        const int row = chunk >> 3, c = chunk & 7, s = (4 - (row & 3)) & 3;
        const float rr = ref[row];
        const float* __restrict__ p = ms + (size_t)row * WID;
        unsigned cnt = 0;
        if (c == 0 && lane < s)
            cnt += (expf(p[lane]) * (rr * src[lane]) > thres) ? 1u : 0u;
        const int col0 = c * 1024 + s + lane;
#pragma unroll
        for (int it = 0; it < 32; ++it) {
            const int col = col0 + it * 32;
            if (col < NPTS)
                cnt += (expf(p[col]) * (rr * src[col]) > thres) ? 1u : 0u;
        }
#pragma unroll
        for (int o = 16; o; o >>= 1) cnt += __shfl_xor_sync(0xffffffffu, cnt, o);
        if (lane == 0) s_cnt[w * 32 + i] = cnt;
    }
    __syncthreads();
    {
        unsigned v = s_cnt[t], x = v;
#pragma unroll
        for (int o = 1; o < 32; o <<= 1) { unsigned y = __shfl_up_sync(0xffffffffu, x, o); if (lane >= o) x += y; }
        if (lane == 31) s_wsum[w] = x;
        __syncthreads();
        if (w == 0) {
            unsigned a = s_wsum[lane], y = a;
#pragma unroll
            for (int o = 1; o < 32; o <<= 1) { unsigned z = __shfl_up_sync(0xffffffffu, y, o); if (lane >= o) y += z; }
            s_wsum[lane] = y - a;
            if (lane == 31) s_tot = y;
        }
        __syncthreads();
        d_coff[blockIdx.x * 1024 + t] = x - v + s_wsum[w];
    }
    if (t == 0) {
        d_btot[blockIdx.x] = s_tot;
        __threadfence();
        s_last = (atomicAdd(&d_tkC, 1u) == gridDim.x - 1) ? 1u : 0u;
    }
    __syncthreads();
    if (s_last) {
        if (t < 64) s_cnt[t] = atomicAdd(&d_btot[t], 0u);
        __syncthreads();
        if (t == 0) {
            unsigned run = 0;
            for (int j = 0; j < 64; ++j) { unsigned cc = s_cnt[j]; d_bbase[j] = run; run += cc; }
            d_ncand = run;
            d_tkC   = 0u;
            __threadfence();
            atomicExch(&d_flagB, 1u);
        }
    }
    if (t == 0) { while (atomicAdd(&d_flagB, 0u) == 0u) __nanosleep(100); }
    __syncthreads();
    __threadfence();

    // ---------------- phase C: ordered output + padding ----------------
    const unsigned lim = (unsigned)min(seg, NPTS);
    act = act0;
    while (act) {
        const int i = __ffs(act) - 1; act &= act - 1;
        const int chunk = chunk0 + i;
        const int row = chunk >> 3, c = chunk & 7, s = (4 - (row & 3)) & 3;
        const float rr = ref[row];
        const float* __restrict__ p = ms + (size_t)row * WID;
        unsigned pos = d_bbase[chunk >> 10] + d_coff[chunk];
        if (c == 0) {                   // head cols first (row-major order)
            const bool hp = (lane < s) && (expf(p[lane]) * (rr * src[lane]) > thres);
            const unsigned mk = __ballot_sync(0xffffffffu, hp);
            if (hp) {
                const unsigned slot = pos + __popc(mk & ((1u << lane) - 1u));
                if (slot < lim) {
                    out[slot]           = (float)row;
                    out[seg + slot]     = (float)lane;
                    out[2 * seg + slot] = expf(p[lane]) * (rr * src[lane]);
                }
            }
            pos += (unsigned)__popc(mk);
        }
        const int col0 = c * 1024 + s + lane;
#pragma unroll
        for (int it = 0; it < 32; ++it) {
            const int col = col0 + it * 32;
            float v = 0.0f;
            bool pred = false;
            if (col < NPTS) {
                v = expf(p[col]) * (rr * src[col]);
                pred = (v > thres);
            }
            const unsigned mk = __ballot_sync(0xffffffffu, pred);
            if (pred) {
                const unsigned slot = pos + __popc(mk & ((1u << lane) - 1u));
                if (slot < lim) {
                    out[slot]           = (float)row;
                    out[seg + slot]     = (float)col;
                    out[2 * seg + slot] = v;
                }
            }
            pos += (unsigned)__popc(mk);
        }
    }
    // padding: valid = idx < count
    {
        const unsigned start = min(d_ncand, lim);
        const unsigned gtid = blockIdx.x * 1024 + t, gsz = gridDim.x * 1024;
        for (unsigned i2 = start + gtid; i2 < (unsigned)seg; i2 += gsz) {
            out[i2] = -1.0f; out[seg + i2] = -1.0f; out[2 * seg + i2] = 0.0f;
        }
    }
    // final reset of flags (all blocks are past both polls)
    __syncthreads();
    if (t == 0) {
        if (atomicAdd(&d_tkD, 1u) == gridDim.x - 1) {
            d_flagA = 0u; d_flagB = 0u; d_tkD = 0u;
            __threadfence();
        }
    }
}

// ---------------- launch ----------------
extern "C" void kernel_launch(void* const* d_in, const int* in_sizes, int n_in,
                              void* d_out, int out_size) {
    const float* ms  = (const float*)d_in[0];
    const float* ref = (const float*)d_in[1];
    const float* src = (const float*)d_in[2];
    float* out = (float*)d_out;
    const int seg = out_size / 3;

    k_init  <<<32, 256>>>(ref, src);
    k_pass1 <<<1024, 256>>>(ms);
    k_sparse<<<64, 1024>>>(ms, ref, src, out, seg);
}

// round 10
// speedup vs baseline: 3.6158x; 1.8356x over previous
#include <cuda_runtime.h>
#include <math_constants.h>

#define NPTS   8192
#define WID    8193
#define NCH    65536          // 8192 rows * 8 chunks (shifted windows)
#define NT     64
#define KCORR  2048
#define MARGIN 1e-4f
#define EPS    1e-4f
#define LOGNEG (-1e30f)
#define NB     128            // sparse-kernel blocks
#define NTHR   512            // sparse-kernel threads
#define NW     (NTHR / 32)    // 16 warps

// ------------- device scratch (zero-init at load; kernels restore what they dirty)
__device__ float    d_logs4[4][NPTS];    // pass1: copy s = logf(src[j+s]) / pad
__device__ float    d_logsp[NPTS + 8];   // sparse: logf(src[j]), padded LOGNEG
__device__ float    d_logr[NPTS];
__device__ float    d_chunkmax[NCH];
__device__ unsigned d_chist[NT];
__device__ unsigned d_ehist[NT];
__device__ unsigned d_tkA, d_tkB, d_tkC, d_tkD;
__device__ unsigned d_flagA, d_flagB;
__device__ unsigned d_nl, d_pick;
__device__ float    d_thres;
__device__ unsigned d_coff[NCH];
__device__ unsigned d_btot[NB];
__device__ unsigned d_bbase[NB];
__device__ unsigned d_ncand;

__device__ __forceinline__ float table_at(int n) {
    float tv = 0.5f;                    // exact fp32 replication of t -= 0.01f
    for (int j = 0; j < n; ++j) tv -= 0.01f;
    return tv;
}

// first n with logt[n] + bias < L   (logt[NT-1] = LOGNEG guarantees a hit)
__device__ __forceinline__ int bin_log(const float* logt, float L, float bias) {
    int lo = 0, hi = NT - 1;
    while (lo < hi) { int mid = (lo + hi) >> 1; if (logt[mid] + bias < L) hi = mid; else lo = mid + 1; }
    return lo;
}

// ==================== K0: log tables ====================
__global__ void k_init(const float* __restrict__ ref, const float* __restrict__ src) {
    const int i = blockIdx.x * 256 + threadIdx.x;   // 0..8191
    if (i < NPTS) {
        d_logr[i]  = logf(ref[i]);
        d_logsp[i] = logf(src[i]);
#pragma unroll
        for (int s = 0; s < 4; ++s)
            d_logs4[s][i] = (i + s < NPTS) ? logf(src[i + s]) : LOGNEG;
    }
    if (i < 8) d_logsp[NPTS + i] = LOGNEG;
}

// ==================== K1: single full 268MB pass, float4 ====================
__global__ void __launch_bounds__(256) k_pass1(const float* __restrict__ ms) {
    __shared__ float    s_logt[NT];
    __shared__ unsigned s_h[NT];
    __shared__ unsigned s_last;
    const int c = blockIdx.x & 7, rg = blockIdx.x >> 3, t = threadIdx.x;
    if (t < NT) {
        const float tv = table_at(t);
        s_logt[t] = (tv > 0.0f) ? logf(tv) : LOGNEG;
        s_h[t] = 0u;
    }
    __syncthreads();

    const int lane = t & 31, w = t >> 5;
    for (int rr = 0; rr < 8; ++rr) {
        const int row = rg * 64 + w * 8 + rr;
        const int s = (4 - (row & 3)) & 3;
        const float4* __restrict__ p4 =
            (const float4*)(ms + (size_t)row * WID + c * 1024 + s);
        const float4* __restrict__ q4 = (const float4*)(&d_logs4[s][c * 1024]);
        float m = -CUDART_INF_F;
#pragma unroll
        for (int k = 0; k < 8; ++k) {
            const float4 a = p4[k * 32 + lane];
            const float4 b = q4[k * 32 + lane];
            m = fmaxf(m, fmaxf(fmaxf(a.x + b.x, a.y + b.y),
                               fmaxf(a.z + b.z, a.w + b.w)));
        }
        if (c == 0 && lane < s)
            m = fmaxf(m, ms[(size_t)row * WID + lane] + d_logs4[0][lane]);
        m += d_logr[row];
#pragma unroll
        for (int o = 16; o; o >>= 1) m = fmaxf(m, __shfl_xor_sync(0xffffffffu, m, o));
        if (lane == 0) {
            d_chunkmax[row * 8 + c] = m;
            int lo = 0, hi = NT;
            while (lo < hi) { int mid = (lo + hi) >> 1; if (s_logt[mid] + MARGIN < m) hi = mid; else lo = mid + 1; }
            if (lo < NT) atomicAdd(&s_h[lo], 1u);
        }
    }
    __syncthreads();
    if (t < NT && s_h[t]) atomicAdd(&d_chist[t], s_h[t]);
    __threadfence();
    __syncthreads();
    if (t == 0) s_last = (atomicAdd(&d_tkA, 1u) == gridDim.x - 1) ? 1u : 0u;
    __syncthreads();
    if (s_last) {
        if (t < NT) s_h[t] = atomicAdd(&d_chist[t], 0u);
        __syncthreads();
        if (t == 0) {
            unsigned cum = 0; int nl = NT - 1;
            for (int n = 0; n < NT; ++n) { cum += s_h[n]; if (cum >= KCORR) { nl = n; break; } }
            d_nl  = (unsigned)nl;
            d_tkA = 0u;
        }
        if (t < NT) d_chist[t] = 0u;
    }
}

// ==================== K2: fused sparse pipeline, log-domain predicates =======
__global__ void __launch_bounds__(NTHR) k_sparse(const float* __restrict__ ms,
                                                 const float* __restrict__ ref,
                                                 const float* __restrict__ src,
                                                 float* __restrict__ out, int seg) {
    __shared__ float    tt[NT];
    __shared__ float    lt[NT];
    __shared__ unsigned h[NT];
    __shared__ unsigned s_cnt[NTHR];
    __shared__ unsigned s_wsum[NW];
    __shared__ unsigned s_tot;
    __shared__ unsigned s_last;
    const int t = threadIdx.x, lane = t & 31, w = t >> 5;
    const int chunk0 = blockIdx.x * NTHR + w * 32;
    if (t < NT) {
        const float tv = table_at(t);
        tt[t] = tv;
        lt[t] = (tv > 0.0f) ? logf(tv) : LOGNEG;
        h[t] = 0u;
    }
    __syncthreads();

    const int nl = (int)d_nl;
    const float cutL  = lt[nl] - MARGIN;
    const float gateA = lt[nl] - EPS;
    const unsigned act0 = __ballot_sync(0xffffffffu, d_chunkmax[chunk0 + lane] > cutL);

    // ---------------- phase A: exact element histogram (log-domain binning) ---
    unsigned act = act0;
    while (act) {
        const int i = __ffs(act) - 1; act &= act - 1;
        const int chunk = chunk0 + i;
        const int row = chunk >> 3, c = chunk & 7, s = (4 - (row & 3)) & 3;
        const float lr = d_logr[row];
        const float* __restrict__ p = ms + (size_t)row * WID;
        if (c == 0 && lane < s) {
            const float L = (p[lane] + d_logsp[lane]) + lr;
            if (L > gateA) {
                int b1 = bin_log(lt, L, EPS), b2 = bin_log(lt, L, -EPS), bin = b1;
                if (b1 != b2) {
                    const float v = expf(p[lane]) * (ref[row] * src[lane]);
                    int lo = 0, hi = NT - 1;
                    while (lo < hi) { int mid = (lo + hi) >> 1; if (tt[mid] < v) hi = mid; else lo = mid + 1; }
                    bin = lo;
                }
                atomicAdd(&h[bin], 1u);
            }
        }
        const int col0 = c * 1024 + s + lane;
        float Ls[32];
#pragma unroll
        for (int it = 0; it < 32; ++it) {
            const int col = col0 + it * 32;                 // pads give L=-1e30
            Ls[it] = (p[col] + d_logsp[col]) + lr;
        }
#pragma unroll
        for (int it = 0; it < 32; ++it) {
            if (Ls[it] > gateA) {
                int b1 = bin_log(lt, Ls[it], EPS), b2 = bin_log(lt, Ls[it], -EPS), bin = b1;
                if (b1 != b2) {
                    const int col = col0 + it * 32;
                    const float v = expf(p[col]) * (ref[row] * src[col]);
                    int lo = 0, hi = NT - 1;
                    while (lo < hi) { int mid = (lo + hi) >> 1; if (tt[mid] < v) hi = mid; else lo = mid + 1; }
                    bin = lo;
                }
                atomicAdd(&h[bin], 1u);
            }
        }
    }
    __syncthreads();
    if (t < NT && h[t]) atomicAdd(&d_ehist[t], h[t]);
    __threadfence();
    __syncthreads();
    if (t == 0) s_last = (atomicAdd(&d_tkB, 1u) == gridDim.x - 1) ? 1u : 0u;
    __syncthreads();
    if (s_last) {
        if (t < NT) h[t] = atomicAdd(&d_ehist[t], 0u);
        __syncthreads();
        if (t == 0) {
            unsigned cum = 0; int pick = NT - 1;
            for (int n = 0; n < NT; ++n) { cum += h[n]; if (cum >= KCORR) { pick = n; break; } }
            d_pick  = (unsigned)pick;
            d_thres = tt[pick];
            d_tkB   = 0u;
        }
        if (t < NT) d_ehist[t] = 0u;
        __threadfence();
        __syncthreads();
        if (t == 0) atomicExch(&d_flagA, 1u);
    }
    if (t == 0) { while (atomicAdd(&d_flagA, 0u) == 0u) __nanosleep(100); }
    __syncthreads();
    __threadfence();
    const int pick = (int)d_pick;
    const float thres = d_thres;
    const float lHi = lt[pick] + EPS, lLo = lt[pick] - EPS;

    // ---------------- phase B: count at thres + scan + base scan --------------
    s_cnt[t] = 0u;
    act = act0;
    while (act) {
        const int i = __ffs(act) - 1; act &= act - 1;
        const int chunk = chunk0 + i;
        const int row = chunk >> 3, c = chunk & 7, s = (4 - (row & 3)) & 3;
        const float lr = d_logr[row];
        const float* __restrict__ p = ms + (size_t)row * WID;
        unsigned cnt = 0;
        if (c == 0 && lane < s) {
            const float L = (p[lane] + d_logsp[lane]) + lr;
            if (L > lHi) ++cnt;
            else if (L > lLo)
                cnt += (expf(p[lane]) * (ref[row] * src[lane]) > thres) ? 1u : 0u;
        }
        const int col0 = c * 1024 + s + lane;
        float Ls[32];
#pragma unroll
        for (int it = 0; it < 32; ++it)
            Ls[it] = (p[col0 + it * 32] + d_logsp[col0 + it * 32]) + lr;
#pragma unroll
        for (int it = 0; it < 32; ++it) {
            if (Ls[it] > lHi) ++cnt;
            else if (Ls[it] > lLo) {
                const int col = col0 + it * 32;
                cnt += (expf(p[col]) * (ref[row] * src[col]) > thres) ? 1u : 0u;
            }
        }
#pragma unroll
        for (int o = 16; o; o >>= 1) cnt += __shfl_xor_sync(0xffffffffu, cnt, o);
        if (lane == 0) s_cnt[w * 32 + i] = cnt;
    }
    __syncthreads();
    {
        unsigned v = s_cnt[t], x = v;
#pragma unroll
        for (int o = 1; o < 32; o <<= 1) { unsigned y = __shfl_up_sync(0xffffffffu, x, o); if (lane >= o) x += y; }
        if (lane == 31) s_wsum[w] = x;
        __syncthreads();
        if (w == 0) {                               // ALL 32 lanes participate
            const unsigned a = (lane < NW) ? s_wsum[lane] : 0u;
            unsigned y = a;
#pragma unroll
            for (int o = 1; o < 32; o <<= 1) { unsigned z = __shfl_up_sync(0xffffffffu, y, o); if (lane >= o) y += z; }
            if (lane < NW) s_wsum[lane] = y - a;
            if (lane == NW - 1) s_tot = y;
        }
        __syncthreads();
        d_coff[blockIdx.x * NTHR + t] = x - v + s_wsum[w];
    }
    if (t == 0) {
        d_btot[blockIdx.x] = s_tot;
        __threadfence();
        s_last = (atomicAdd(&d_tkC, 1u) == gridDim.x - 1) ? 1u : 0u;
    }
    __syncthreads();
    if (s_last) {
        if (t < NB) s_cnt[t] = atomicAdd(&d_btot[t], 0u);
        __syncthreads();
        if (t == 0) {
            unsigned run = 0;
            for (int j = 0; j < NB; ++j) { unsigned cc = s_cnt[j]; d_bbase[j] = run; run += cc; }
            d_ncand = run;
            d_tkC   = 0u;
            __threadfence();
            atomicExch(&d_flagB, 1u);
        }
    }
    if (t == 0) { while (atomicAdd(&d_flagB, 0u) == 0u) __nanosleep(100); }
    __syncthreads();
    __threadfence();

    // ---------------- phase C: ordered output + padding ----------------
    const unsigned lim = (unsigned)min(seg, NPTS);
    act = act0;
    while (act) {
        const int i = __ffs(act) - 1; act &= act - 1;
        const int chunk = chunk0 + i;
        const int row = chunk >> 3, c = chunk & 7, s = (4 - (row & 3)) & 3;
        const float lr = d_logr[row];
        const float* __restrict__ p = ms + (size_t)row * WID;
        unsigned pos = d_bbase[chunk >> 9] + d_coff[chunk];
        if (c == 0) {
            bool hp = false;
            if (lane < s) {
                const float L = (p[lane] + d_logsp[lane]) + lr;
                hp = (L > lHi) || (L > lLo &&
                     expf(p[lane]) * (ref[row] * src[lane]) > thres);
            }
            const unsigned mk = __ballot_sync(0xffffffffu, hp);
            if (hp) {
                const unsigned slot = pos + __popc(mk & ((1u << lane) - 1u));
                if (slot < lim) {
                    out[slot]           = (float)row;
                    out[seg + slot]     = (float)lane;
                    out[2 * seg + slot] = expf(p[lane]) * (ref[row] * src[lane]);
                }
            }
            pos += (unsigned)__popc(mk);
        }
        const int col0 = c * 1024 + s + lane;
        float Ls[32];
#pragma unroll
        for (int it = 0; it < 32; ++it)
            Ls[it] = (p[col0 + it * 32] + d_logsp[col0 + it * 32]) + lr;
#pragma unroll
        for (int it = 0; it < 32; ++it) {
            const int col = col0 + it * 32;
            bool pred;
            if (Ls[it] > lHi) pred = true;
            else if (Ls[it] > lLo) pred = expf(p[col]) * (ref[row] * src[col]) > thres;
            else pred = false;
            const unsigned mk = __ballot_sync(0xffffffffu, pred);
            if (pred) {
                const unsigned slot = pos + __popc(mk & ((1u << lane) - 1u));
                if (slot < lim) {
                    out[slot]           = (float)row;
                    out[seg + slot]     = (float)col;
                    out[2 * seg + slot] = expf(p[col]) * (ref[row] * src[col]);
                }
            }
            pos += (unsigned)__popc(mk);
        }
    }
    // padding: valid = idx < count
    {
        const unsigned start = min(d_ncand, lim);
        const unsigned gtid = blockIdx.x * NTHR + t, gsz = gridDim.x * NTHR;
        for (unsigned i2 = start + gtid; i2 < (unsigned)seg; i2 += gsz) {
            out[i2] = -1.0f; out[seg + i2] = -1.0f; out[2 * seg + i2] = 0.0f;
        }
    }
    __syncthreads();
    if (t == 0) {
        if (atomicAdd(&d_tkD, 1u) == gridDim.x - 1) {
            d_flagA = 0u; d_flagB = 0u; d_tkD = 0u;
            __threadfence();
        }
    }
}

// ---------------- launch ----------------
extern "C" void kernel_launch(void* const* d_in, const int* in_sizes, int n_in,
                              void* d_out, int out_size) {
    const float* ms  = (const float*)d_in[0];
    const float* ref = (const float*)d_in[1];
    const float* src = (const float*)d_in[2];
    float* out = (float*)d_out;
    const int seg = out_size / 3;

    k_init  <<<32, 256>>>(ref, src);
    k_pass1 <<<1024, 256>>>(ms);
    k_sparse<<<NB, NTHR>>>(ms, ref, src, out, seg);
}

// round 11
// speedup vs baseline: 3.6813x; 1.0181x over previous
#include <cuda_runtime.h>
#include <math_constants.h>

#define NPTS   8192
#define WID    8193
#define NCH    65536          // 8192 rows * 8 chunks (shifted windows)
#define NT     64
#define KCORR  2048
#define MARGIN 1e-4f
#define LOGNEG (-1e30f)
#define NB     128            // sparse-kernel blocks (co-resident on 148 SMs)
#define NTHR   512
#define CAPC   (1 << 17)      // candidate buffer
#define SKEYS  12288          // smem key cache

// ------------- device scratch (zero-init at load; kernels restore what they dirty)
__device__ float    d_logs4[4][NPTS];    // pass1: copy s = logf(src[j+s]) / pad
__device__ float    d_logsp[NPTS + 8];   // sparse: logf(src[j]), padded LOGNEG
__device__ float    d_logr[NPTS];
__device__ float    d_chunkmax[NCH];
__device__ unsigned d_chist[NT];
__device__ unsigned d_ehist[NT];
__device__ unsigned d_tkA, d_tkB, d_tkC, d_tkD;
__device__ unsigned d_flagA, d_flagB;
__device__ unsigned d_nl;
__device__ float    d_thres;
__device__ unsigned d_nsel;              // exact selected count (from hist)
__device__ unsigned d_nc;                // candidate counter
__device__ unsigned d_ckey[CAPC];
__device__ float    d_cv[CAPC];

__device__ __forceinline__ float table_at(int n) {
    float tv = 0.5f;                     // exact fp32 replication of t -= 0.01f
    for (int j = 0; j < n; ++j) tv -= 0.01f;
    return tv;
}

// ==================== K0: log tables ====================
__global__ void k_init(const float* __restrict__ ref, const float* __restrict__ src) {
    const int i = blockIdx.x * 256 + threadIdx.x;   // 0..8191
    if (i < NPTS) {
        d_logr[i]  = logf(ref[i]);
        d_logsp[i] = logf(src[i]);
#pragma unroll
        for (int s = 0; s < 4; ++s)
            d_logs4[s][i] = (i + s < NPTS) ? logf(src[i + s]) : LOGNEG;
    }
    if (i < 8) d_logsp[NPTS + i] = LOGNEG;
}

// ==================== K1: single full 268MB pass, float4 (unchanged) =========
__global__ void __launch_bounds__(256) k_pass1(const float* __restrict__ ms) {
    __shared__ float    s_logt[NT];
    __shared__ unsigned s_h[NT];
    __shared__ unsigned s_last;
    const int c = blockIdx.x & 7, rg = blockIdx.x >> 3, t = threadIdx.x;
    if (t < NT) {
        const float tv = table_at(t);
        s_logt[t] = (tv > 0.0f) ? logf(tv) : LOGNEG;
        s_h[t] = 0u;
    }
    __syncthreads();

    const int lane = t & 31, w = t >> 5;
    for (int rr = 0; rr < 8; ++rr) {
        const int row = rg * 64 + w * 8 + rr;
        const int s = (4 - (row & 3)) & 3;
        const float4* __restrict__ p4 =
            (const float4*)(ms + (size_t)row * WID + c * 1024 + s);
        const float4* __restrict__ q4 = (const float4*)(&d_logs4[s][c * 1024]);
        float m = -CUDART_INF_F;
#pragma unroll
        for (int k = 0; k < 8; ++k) {
            const float4 a = p4[k * 32 + lane];
            const float4 b = q4[k * 32 + lane];
            m = fmaxf(m, fmaxf(fmaxf(a.x + b.x, a.y + b.y),
                               fmaxf(a.z + b.z, a.w + b.w)));
        }
        if (c == 0 && lane < s)
            m = fmaxf(m, ms[(size_t)row * WID + lane] + d_logs4[0][lane]);
        m += d_logr[row];
#pragma unroll
        for (int o = 16; o; o >>= 1) m = fmaxf(m, __shfl_xor_sync(0xffffffffu, m, o));
        if (lane == 0) {
            d_chunkmax[row * 8 + c] = m;
            int lo = 0, hi = NT;
            while (lo < hi) { int mid = (lo + hi) >> 1; if (s_logt[mid] + MARGIN < m) hi = mid; else lo = mid + 1; }
            if (lo < NT) atomicAdd(&s_h[lo], 1u);
        }
    }
    __syncthreads();
    if (t < NT && s_h[t]) atomicAdd(&d_chist[t], s_h[t]);
    __threadfence();
    __syncthreads();
    if (t == 0) s_last = (atomicAdd(&d_tkA, 1u) == gridDim.x - 1) ? 1u : 0u;
    __syncthreads();
    if (s_last) {
        if (t < NT) s_h[t] = atomicAdd(&d_chist[t], 0u);
        __syncthreads();
        if (t == 0) {
            unsigned cum = 0; int nl = NT - 1;
            for (int n = 0; n < NT; ++n) { cum += s_h[n]; if (cum >= KCORR) { nl = n; break; } }
            d_nl  = (unsigned)nl;
            d_tkA = 0u;
        }
        if (t < NT) d_chist[t] = 0u;
    }
}

// ==================== K2: one sparse walk + rank-ordered emission ============
__global__ void __launch_bounds__(NTHR) k_sparse(const float* __restrict__ ms,
                                                 const float* __restrict__ ref,
                                                 const float* __restrict__ src,
                                                 float* __restrict__ out, int seg) {
    __shared__ float    tt[NT];
    __shared__ unsigned h[NT];
    __shared__ unsigned s_last;
    __shared__ unsigned s_keys[SKEYS];
    const int t = threadIdx.x, lane = t & 31, w = t >> 5;
    if (t < NT) { tt[t] = table_at(t); h[t] = 0u; }
    __syncthreads();

    const int nl = (int)d_nl;
    const float tnl  = tt[nl];
    const float cutL = ((tnl > 0.0f) ? logf(tnl) : LOGNEG) - MARGIN;
    const int chunk0 = blockIdx.x * NTHR + w * 32;

    // ---------------- phase A: ONE walk — extract candidates + exact hist -----
    unsigned act = __ballot_sync(0xffffffffu, d_chunkmax[chunk0 + lane] > cutL);
    while (act) {
        const int i = __ffs(act) - 1; act &= act - 1;
        const int chunk = chunk0 + i;
        const int row = chunk >> 3, c = chunk & 7, s = (4 - (row & 3)) & 3;
        const float lr = d_logr[row];
        const float rr = ref[row];
        const float* __restrict__ p = ms + (size_t)row * WID;

        // head columns [0,s) fold into chunk 0
        if (c == 0) {
            bool pred = false; float v = 0.0f;
            if (lane < s) {
                const float L = (p[lane] + d_logsp[lane]) + lr;
                if (L > cutL) { v = expf(p[lane]) * (rr * src[lane]); pred = true; }
            }
            const unsigned mk = __ballot_sync(0xffffffffu, pred);
            if (mk) {
                unsigned base;
                const int leader = __ffs(mk) - 1;
                if (lane == leader) base = atomicAdd(&d_nc, (unsigned)__popc(mk));
                base = __shfl_sync(0xffffffffu, base, leader);
                if (pred) {
                    const unsigned pos = base + __popc(mk & ((1u << lane) - 1u));
                    if (pos < CAPC) {
                        d_ckey[pos] = ((unsigned)row << 13) | (unsigned)lane;
                        d_cv[pos]   = v;
                    }
                    int lo = 0, hi = NT - 1;          // first n with tt[n] < v
                    while (lo < hi) { int mid = (lo + hi) >> 1; if (tt[mid] < v) hi = mid; else lo = mid + 1; }
                    atomicAdd(&h[lo], 1u);
                }
            }
        }
        const int col0 = c * 1024 + s + lane;
        float Ls[32];
#pragma unroll
        for (int it = 0; it < 32; ++it)               // pads give L = -1e30
            Ls[it] = (p[col0 + it * 32] + d_logsp[col0 + it * 32]) + lr;
#pragma unroll
        for (int it = 0; it < 32; ++it) {
            const bool pred = Ls[it] > cutL;
            const unsigned mk = __ballot_sync(0xffffffffu, pred);
            if (!mk) continue;
            unsigned base;
            const int leader = __ffs(mk) - 1;
            if (lane == leader) base = atomicAdd(&d_nc, (unsigned)__popc(mk));
            base = __shfl_sync(0xffffffffu, base, leader);
            if (pred) {
                const int col = col0 + it * 32;
                const float v = expf(p[col]) * (rr * src[col]);  // exact ref expr
                const unsigned pos = base + __popc(mk & ((1u << lane) - 1u));
                if (pos < CAPC) {
                    d_ckey[pos] = ((unsigned)row << 13) | (unsigned)col;
                    d_cv[pos]   = v;
                }
                int lo = 0, hi = NT - 1;
                while (lo < hi) { int mid = (lo + hi) >> 1; if (tt[mid] < v) hi = mid; else lo = mid + 1; }
                atomicAdd(&h[lo], 1u);
            }
        }
    }
    __syncthreads();
    if (t < NT && h[t]) atomicAdd(&d_ehist[t], h[t]);
    __threadfence();
    __syncthreads();
    if (t == 0) s_last = (atomicAdd(&d_tkB, 1u) == gridDim.x - 1) ? 1u : 0u;
    __syncthreads();
    if (s_last) {
        if (t < NT) h[t] = atomicAdd(&d_ehist[t], 0u);
        __syncthreads();
        if (t == 0) {
            unsigned cum = 0; int pick = NT - 1;
            for (int n = 0; n < NT; ++n) { cum += h[n]; if (cum >= KCORR) { pick = n; break; } }
            d_thres = tt[pick];
            d_nsel  = cum;                 // exact count(thres)
            d_tkB   = 0u;
        }
        if (t < NT) d_ehist[t] = 0u;
        __threadfence();
        __syncthreads();
        if (t == 0) atomicExch(&d_flagA, 1u);
    }
    if (t == 0) { while (atomicAdd(&d_flagA, 0u) == 0u) __nanosleep(100); }
    __syncthreads();
    __threadfence();

    const float thres = d_thres;
    const unsigned C  = min(d_nc, (unsigned)CAPC);
    const unsigned gtid = blockIdx.x * NTHR + t, gsz = gridDim.x * NTHR;

    // ---------------- phase B1: mark selected (bit 31 of key) ----------------
    for (unsigned i = gtid; i < C; i += gsz)
        if (d_cv[i] > thres) d_ckey[i] |= 0x80000000u;
    __threadfence();
    __syncthreads();
    if (t == 0) {
        if (atomicAdd(&d_tkC, 1u) == gridDim.x - 1) {
            d_tkC = 0u;
            __threadfence();
            atomicExch(&d_flagB, 1u);
        }
        while (atomicAdd(&d_flagB, 0u) == 0u) __nanosleep(100);
    }
    __syncthreads();
    __threadfence();

    // ---------------- phase B2: rank-based ordered emission + padding --------
    const bool use_s = (C <= (unsigned)SKEYS);
    if (use_s) for (unsigned j = t; j < C; j += NTHR) s_keys[j] = d_ckey[j];
    __syncthreads();

    const unsigned lim = (unsigned)min(seg, NPTS);
    for (unsigned i = gtid; i < C; i += gsz) {
        const unsigned ki = d_ckey[i];
        if (ki & 0x80000000u) {
            unsigned rank = 0;
            if (use_s) {
                for (unsigned j = 0; j < C; ++j) {
                    const unsigned kj = s_keys[j];
                    rank += (kj > 0x7FFFFFFFu && kj < ki) ? 1u : 0u;
                }
            } else {
                for (unsigned j = 0; j < C; ++j) {
                    const unsigned kj = d_ckey[j];
                    rank += (kj > 0x7FFFFFFFu && kj < ki) ? 1u : 0u;
                }
            }
            if (rank < lim) {
                const unsigned klow = ki & 0x7FFFFFFFu;
                out[rank]           = (float)(klow >> 13);
                out[seg + rank]     = (float)(klow & 8191u);
                out[2 * seg + rank] = d_cv[i];
            }
        }
    }
    // padding: valid = idx < count
    {
        const unsigned start = min(d_nsel, lim);
        for (unsigned i2 = start + gtid; i2 < (unsigned)seg; i2 += gsz) {
            out[i2] = -1.0f; out[seg + i2] = -1.0f; out[2 * seg + i2] = 0.0f;
        }
    }
    // final reset (all blocks are past both polls and all reads of d_nc)
    __syncthreads();
    if (t == 0) {
        if (atomicAdd(&d_tkD, 1u) == gridDim.x - 1) {
            d_flagA = 0u; d_flagB = 0u; d_nc = 0u; d_tkD = 0u;
            __threadfence();
        }
    }
}

// ---------------- launch ----------------
extern "C" void kernel_launch(void* const* d_in, const int* in_sizes, int n_in,
                              void* d_out, int out_size) {
    const float* ms  = (const float*)d_in[0];
    const float* ref = (const float*)d_in[1];
    const float* src = (const float*)d_in[2];
    float* out = (float*)d_out;
    const int seg = out_size / 3;

    k_init  <<<32, 256>>>(ref, src);
    k_pass1 <<<1024, 256>>>(ms);
    k_sparse<<<NB, NTHR>>>(ms, ref, src, out, seg);
}